// round 9
// baseline (speedup 1.0000x reference)
#include <cuda_runtime.h>
#include <math.h>

#define BATCH 4
#define NPTS  4096
#define KNN   16
#define NB    32          // 2*k neighbors per point
#define NPIX  (BATCH*NPTS*NB)

typedef unsigned long long u64;

// ---------------- f32x2 packed helpers (Blackwell FFMA2 path) ----------------
__device__ __forceinline__ u64 fma2(u64 a, u64 b, u64 c) {
    u64 d; asm("fma.rn.f32x2 %0,%1,%2,%3;" : "=l"(d) : "l"(a), "l"(b), "l"(c)); return d;
}
__device__ __forceinline__ u64 add2(u64 a, u64 b) {
    u64 d; asm("add.rn.f32x2 %0,%1,%2;" : "=l"(d) : "l"(a), "l"(b)); return d;
}
__device__ __forceinline__ u64 pack2(float lo, float hi) {
    u64 d; asm("mov.b64 %0,{%1,%2};" : "=l"(d) : "f"(lo), "f"(hi)); return d;
}
__device__ __forceinline__ void unpack2(u64 v, float& lo, float& hi) {
    asm("mov.b64 {%0,%1},%2;" : "=f"(lo), "=f"(hi) : "l"(v));
}

// ---------------- device scratch ----------------
__device__ float4 g_feats[NPIX];        // (resi.x, resi.y, resi.z, dist) per pixel
__device__ float  g_grp[NPIX*3];        // gathered neighbor coords per pixel
__device__ float4 g_r4[2*BATCH*NPTS];   // prepacked refs: (x, y, z, x^2+y^2+z^2)

// ---------------- pack refs with their squared norm ----------------
__global__ __launch_bounds__(256) void pack_k(const float* __restrict__ p1,
                                              const float* __restrict__ p2)
{
    int i = blockIdx.x * 256 + threadIdx.x;     // 0 .. 2*BATCH*NPTS-1
    int phase = i >> 14;                        // BATCH*NPTS = 16384
    int rem   = i & 16383;
    int b     = rem >> 12;
    int r     = rem & (NPTS - 1);
    const float* P = (phase ? p2 : p1) + b * 3 * NPTS;
    float x = P[r], y = P[NPTS + r], z = P[2*NPTS + r];
    g_r4[i] = make_float4(x, y, z, fmaf(x, x, fmaf(y, y, z * z)));
}

// ---------------- KNN: one WARP per query ----------------
// Lane l scans refs t*32+l. Top-16 list replicated in every lane, sorted
// ascending; dl[15] is the warp-global threshold. Ballot-serialized inserts
// are uniform across the warp (no divergence). Systolic sorted-insert: 16
// stages of compare/select; a candidate >= dl[15] passes through as a no-op,
// so stale within-batch ballots are safe.
__global__ __launch_bounds__(256) void knn_w(const float* __restrict__ p1)
{
    const int lane  = threadIdx.x & 31;
    const int wid   = threadIdx.x >> 5;
    const int b     = blockIdx.y;
    const int phase = blockIdx.z;
    const int n     = blockIdx.x * 8 + wid;       // query index

    const float* Q = p1 + b * 3 * NPTS;
    const float qx = Q[n], qy = Q[NPTS + n], qz = Q[2*NPTS + n];

    const float4* __restrict__ R4 = g_r4 + (phase * BATCH + b) * NPTS;

    const float INF = __int_as_float(0x7f800000);
    float dl[KNN];
    int   il[KNN];
    #pragma unroll
    for (int s = 0; s < KNN; s++) { dl[s] = INF; il[s] = 0; }

    for (int t = 0; t < NPTS / 32; t++) {
        float4 rv = R4[t * 32 + lane];
        // compare in the v = rr - 2*dot domain (d2 = v + qq, same ordering)
        float dot = fmaf(qx, rv.x, fmaf(qy, rv.y, qz * rv.z));
        float v   = fmaf(-2.f, dot, rv.w);
        unsigned mask = __ballot_sync(0xffffffffu, v < dl[KNN - 1]);
        while (mask) {
            int src = __ffs(mask) - 1;
            mask &= mask - 1;
            float c  = __shfl_sync(0xffffffffu, v, src);
            int   ci = t * 32 + src;
            // uniform systolic sorted-insert (evicts old max, no-op if c >= dl[15])
            #pragma unroll
            for (int s = 0; s < KNN; s++) {
                bool p = c < dl[s];
                float nv = p ? c  : dl[s];
                int   ni = p ? ci : il[s];
                float cc = p ? dl[s] : c;
                int   cn = p ? il[s] : ci;
                dl[s] = nv; il[s] = ni; c = cc; ci = cn;
            }
        }
    }

    // emit: lanes 0..15 each own one slot (order irrelevant downstream)
    if (lane < KNN) {
        int idx = il[0];
        #pragma unroll
        for (int s = 1; s < KNN; s++)
            if (lane == s) idx = il[s];
        float4 rv = R4[idx];
        float dx = rv.x - qx, dy = rv.y - qy, dz = rv.z - qz;
        float d  = sqrtf(fmaxf(dx*dx + dy*dy + dz*dz, 1e-12f));
        size_t base = ((size_t)(b * NPTS + n)) * NB + phase * KNN + lane;
        g_feats[base] = make_float4(dx, dy, dz, d);
        g_grp[base*3 + 0] = rv.x;
        g_grp[base*3 + 1] = rv.y;
        g_grp[base*3 + 2] = rv.z;
    }
}

// ---------------- fused fold + MLP + max + softmax + weighted sum --------------
// (unchanged from round 7: validated at 316.6 us)
#define SMEMF 13056

__device__ __forceinline__ void layer01(float4 x,
                                        const float* __restrict__ sW0,
                                        const float* __restrict__ sb0,
                                        const float* __restrict__ sW1,
                                        const float* __restrict__ sb1,
                                        u64 h1p[32])
{
    u64 h0p[32];
    #pragma unroll 4
    for (int c = 0; c < 64; c += 2) {
        float4 wa = ((const float4*)sW0)[c];
        float4 wb = ((const float4*)sW0)[c + 1];
        float a = fmaf(wa.x, x.x, fmaf(wa.y, x.y, fmaf(wa.z, x.z, fmaf(wa.w, x.w, sb0[c]))));
        float b = fmaf(wb.x, x.x, fmaf(wb.y, x.y, fmaf(wb.z, x.z, fmaf(wb.w, x.w, sb0[c+1]))));
        h0p[c >> 1] = pack2(fmaxf(a, 0.f), fmaxf(b, 0.f));
    }
    #pragma unroll 2
    for (int c = 0; c < 64; c += 2) {
        const ulonglong2* wr0 = (const ulonglong2*)(sW1 + c * 64);
        const ulonglong2* wr1 = (const ulonglong2*)(sW1 + (c + 1) * 64);
        u64 a0 = 0ull, a1 = 0ull, b0 = 0ull, b1 = 0ull;
        #pragma unroll
        for (int j = 0; j < 16; j++) {
            ulonglong2 w0 = wr0[j];
            ulonglong2 w1 = wr1[j];
            a0 = fma2(w0.x, h0p[2*j],     a0);
            a1 = fma2(w0.y, h0p[2*j + 1], a1);
            b0 = fma2(w1.x, h0p[2*j],     b0);
            b1 = fma2(w1.y, h0p[2*j + 1], b1);
        }
        float alo, ahi, blo, bhi;
        unpack2(add2(a0, a1), alo, ahi);
        unpack2(add2(b0, b1), blo, bhi);
        h1p[c >> 1] = pack2(fmaxf(sb1[c]   + alo + ahi, 0.f),
                            fmaxf(sb1[c+1] + blo + bhi, 0.f));
    }
}

__global__ __launch_bounds__(128) void mlp_k(float* __restrict__ out,
    const float* __restrict__ w0, const float* __restrict__ b0,
    const float* __restrict__ g0, const float* __restrict__ be0,
    const float* __restrict__ m0, const float* __restrict__ v0,
    const float* __restrict__ w1, const float* __restrict__ b1,
    const float* __restrict__ g1, const float* __restrict__ be1,
    const float* __restrict__ m1, const float* __restrict__ v1,
    const float* __restrict__ w2, const float* __restrict__ b2,
    const float* __restrict__ g2, const float* __restrict__ be2,
    const float* __restrict__ m2, const float* __restrict__ v2)
{
    extern __shared__ float sm[];
    float* sW1 = sm;
    float* sW2 = sm + 4096;
    float* sW0 = sm + 12288;
    float* sb0 = sm + 12544;
    float* sb1 = sm + 12608;
    float* sb2 = sm + 12672;
    float* sS0 = sm + 12800;
    float* sS1 = sm + 12864;
    float* sS2 = sm + 12928;

    const int tid = threadIdx.x;

    if (tid < 64) {
        float s = g0[tid] * rsqrtf(v0[tid] + 1e-3f);
        sS0[tid] = s; sb0[tid] = (b0[tid] - m0[tid]) * s + be0[tid];
        float t = g1[tid] * rsqrtf(v1[tid] + 1e-3f);
        sS1[tid] = t; sb1[tid] = (b1[tid] - m1[tid]) * t + be1[tid];
    }
    if (tid < 128) {
        float s = g2[tid] * rsqrtf(v2[tid] + 1e-3f);
        sS2[tid] = s; sb2[tid] = (b2[tid] - m2[tid]) * s + be2[tid];
    }
    __syncthreads();
    for (int i = tid; i < 4096; i += 128) sW1[i] = w1[i] * sS1[i >> 6];
    for (int i = tid; i < 8192; i += 128) sW2[i] = w2[i] * sS2[i >> 6];
    for (int i = tid; i < 256;  i += 128) sW0[i] = w0[i] * sS0[i >> 2];
    __syncthreads();

    const int warp = tid >> 5;
    const int lane = tid & 31;
    const int pt   = blockIdx.x * 8 + warp * 2 + (lane >> 4);
    const int nb   = lane & 15;

    const size_t pixA = (size_t)pt * NB + nb;
    const size_t pixB = pixA + 16;

    u64 h1pA[32], h1pB[32];
    layer01(g_feats[pixA], sW0, sb0, sW1, sb1, h1pA);
    layer01(g_feats[pixB], sW0, sb0, sW1, sb1, h1pB);

    float mxA = -__int_as_float(0x7f800000);
    float mxB = mxA;
    #pragma unroll 2
    for (int c = 0; c < 128; c++) {
        const ulonglong2* wr = (const ulonglong2*)(sW2 + c * 64);
        u64 a0 = 0ull, a1 = 0ull, c0 = 0ull, c1 = 0ull;
        #pragma unroll
        for (int j = 0; j < 16; j++) {
            ulonglong2 w = wr[j];
            a0 = fma2(w.x, h1pA[2*j],     a0);
            a1 = fma2(w.y, h1pA[2*j + 1], a1);
            c0 = fma2(w.x, h1pB[2*j],     c0);
            c1 = fma2(w.y, h1pB[2*j + 1], c1);
        }
        float alo, ahi, blo, bhi;
        unpack2(add2(a0, a1), alo, ahi);
        unpack2(add2(c0, c1), blo, bhi);
        float bias = sb2[c];
        mxA = fmaxf(mxA, fmaxf(bias + alo + ahi, 0.f));
        mxB = fmaxf(mxB, fmaxf(bias + blo + bhi, 0.f));
    }

    float M = fmaxf(mxA, mxB);
    #pragma unroll
    for (int o = 8; o; o >>= 1) M = fmaxf(M, __shfl_xor_sync(0xffffffffu, M, o));
    float eA = expf(mxA - M);
    float eB = expf(mxB - M);
    float S = eA + eB;
    #pragma unroll
    for (int o = 8; o; o >>= 1) S += __shfl_xor_sync(0xffffffffu, S, o);
    float wA = eA / S;
    float wB = eB / S;

    size_t ga = pixA * 3, gb = pixB * 3;
    float sx = fmaf(wA, g_grp[ga + 0], wB * g_grp[gb + 0]);
    float sy = fmaf(wA, g_grp[ga + 1], wB * g_grp[gb + 1]);
    float sz = fmaf(wA, g_grp[ga + 2], wB * g_grp[gb + 2]);
    #pragma unroll
    for (int o = 8; o; o >>= 1) {
        sx += __shfl_xor_sync(0xffffffffu, sx, o);
        sy += __shfl_xor_sync(0xffffffffu, sy, o);
        sz += __shfl_xor_sync(0xffffffffu, sz, o);
    }
    if (nb == 0) {
        int b = pt >> 12;
        int n = pt & (NPTS - 1);
        out[(b*3 + 0) * NPTS + n] = sx;
        out[(b*3 + 1) * NPTS + n] = sy;
        out[(b*3 + 2) * NPTS + n] = sz;
    }
}

// ---------------- launch ----------------
extern "C" void kernel_launch(void* const* d_in, const int* in_sizes, int n_in,
                              void* d_out, int out_size)
{
    const float* p1 = (const float*)d_in[0];
    const float* p2 = (const float*)d_in[1];
    // d_in[2] = k (fixed at 16)
    const float* w0  = (const float*)d_in[3];
    const float* b0  = (const float*)d_in[4];
    const float* g0  = (const float*)d_in[5];
    const float* be0 = (const float*)d_in[6];
    const float* m0  = (const float*)d_in[7];
    const float* v0  = (const float*)d_in[8];
    const float* w1  = (const float*)d_in[9];
    const float* b1  = (const float*)d_in[10];
    const float* g1  = (const float*)d_in[11];
    const float* be1 = (const float*)d_in[12];
    const float* m1  = (const float*)d_in[13];
    const float* v1  = (const float*)d_in[14];
    const float* w2  = (const float*)d_in[15];
    const float* b2  = (const float*)d_in[16];
    const float* g2  = (const float*)d_in[17];
    const float* be2 = (const float*)d_in[18];
    const float* m2  = (const float*)d_in[19];
    const float* v2  = (const float*)d_in[20];

    cudaFuncSetAttribute(mlp_k, cudaFuncAttributeMaxDynamicSharedMemorySize,
                         SMEMF * (int)sizeof(float));

    pack_k<<<2*BATCH*NPTS/256, 256>>>(p1, p2);

    knn_w<<<dim3(NPTS/8, BATCH, 2), 256>>>(p1);

    mlp_k<<<BATCH*NPTS/8, 128, SMEMF * (int)sizeof(float)>>>((float*)d_out,
        w0, b0, g0, be0, m0, v0,
        w1, b1, g1, be1, m1, v1,
        w2, b2, g2, be2, m2, v2);
}

// round 10
// speedup vs baseline: 1.8295x; 1.8295x over previous
#include <cuda_runtime.h>
#include <math.h>

#define BATCH 4
#define NPTS  4096
#define KNN   16
#define NB    32          // 2*k neighbors per point
#define NPIX  (BATCH*NPTS*NB)

typedef unsigned long long u64;

// ---------------- f32x2 packed helpers (Blackwell FFMA2 path) ----------------
__device__ __forceinline__ u64 fma2(u64 a, u64 b, u64 c) {
    u64 d; asm("fma.rn.f32x2 %0,%1,%2,%3;" : "=l"(d) : "l"(a), "l"(b), "l"(c)); return d;
}
__device__ __forceinline__ u64 add2(u64 a, u64 b) {
    u64 d; asm("add.rn.f32x2 %0,%1,%2;" : "=l"(d) : "l"(a), "l"(b)); return d;
}
__device__ __forceinline__ u64 pack2(float lo, float hi) {
    u64 d; asm("mov.b64 %0,{%1,%2};" : "=l"(d) : "f"(lo), "f"(hi)); return d;
}
__device__ __forceinline__ void unpack2(u64 v, float& lo, float& hi) {
    asm("mov.b64 {%0,%1},%2;" : "=f"(lo), "=f"(hi) : "l"(v));
}

// ---------------- device scratch ----------------
__device__ float4 g_feats[NPIX];        // (resi.x, resi.y, resi.z, dist) per pixel
__device__ float  g_grp[NPIX*3];        // gathered neighbor coords per pixel
__device__ float4 g_r4[2*BATCH*NPTS];   // prepacked refs: (x, y, z, x^2+y^2+z^2)

// ---------------- pack refs with their squared norm ----------------
__global__ __launch_bounds__(256) void pack_k(const float* __restrict__ p1,
                                              const float* __restrict__ p2)
{
    int i = blockIdx.x * 256 + threadIdx.x;     // 0 .. 2*BATCH*NPTS-1
    int phase = i >> 14;                        // BATCH*NPTS = 16384
    int rem   = i & 16383;
    int b     = rem >> 12;
    int r     = rem & (NPTS - 1);
    const float* P = (phase ? p2 : p1) + b * 3 * NPTS;
    float x = P[r], y = P[NPTS + r], z = P[2*NPTS + r];
    g_r4[i] = make_float4(x, y, z, fmaf(x, x, fmaf(y, y, z * z)));
}

// ---------------- KNN: one WARP per query, warp-DISTRIBUTED sorted top-16 ----------------
// Lane i (i<16) holds slot i of the sorted-ascending top-16 (dl, il). Threshold
// is shfl(dl,15). All 32 lanes scan refs tile-staged in smem; ballot hits are
// serialized, each insert is a warp shift-and-place (~13 instr, no long chain).
// Inserts self-guard (no-op when c >= dl[15]) so stale within-batch ballots are safe.
#define KTILE 2048

__global__ __launch_bounds__(256) void knn_w(const float* __restrict__ p1)
{
    const int lane  = threadIdx.x & 31;
    const int wid   = threadIdx.x >> 5;
    const int b     = blockIdx.y;
    const int phase = blockIdx.z;
    const int n     = blockIdx.x * 8 + wid;       // query index

    const float* Q = p1 + b * 3 * NPTS;
    const float qx = Q[n], qy = Q[NPTS + n], qz = Q[2*NPTS + n];

    const float4* __restrict__ R4 = g_r4 + (phase * BATCH + b) * NPTS;

    const float INF = __int_as_float(0x7f800000);
    float dl = INF;   // slot (lane) value, v-domain
    int   il = 0;     // slot (lane) ref index

    __shared__ float4 sref[KTILE];

    for (int t0 = 0; t0 < NPTS; t0 += KTILE) {
        for (int i = threadIdx.x; i < KTILE; i += 256)
            sref[i] = R4[t0 + i];
        __syncthreads();

        for (int tt = 0; tt < KTILE / 32; tt++) {
            const int tbase = t0 + tt * 32;
            float4 rv = sref[tt * 32 + lane];
            // compare in the v = rr - 2*dot domain (d2 = v + qq, same ordering)
            float dot = fmaf(qx, rv.x, fmaf(qy, rv.y, qz * rv.z));
            float v   = fmaf(-2.f, dot, rv.w);
            float thr = __shfl_sync(0xffffffffu, dl, 15);
            unsigned mask = __ballot_sync(0xffffffffu, v < thr);
            while (mask) {
                int src = __ffs(mask) - 1;
                mask &= mask - 1;
                float c  = __shfl_sync(0xffffffffu, v, src);
                int   ci = tbase + src;
                float up  = __shfl_up_sync(0xffffffffu, dl, 1);
                int   upi = __shfl_up_sync(0xffffffffu, il, 1);
                bool  p   = c < dl;
                unsigned bp = __ballot_sync(0xffffffffu, p);
                bool  pu  = lane ? ((bp >> (lane - 1)) & 1u) : false;
                dl = p ? (pu ? up  : c ) : dl;
                il = p ? (pu ? upi : ci) : il;
            }
        }
        __syncthreads();
    }

    // emit: lane i owns slot i (neighbor order irrelevant downstream)
    if (lane < KNN) {
        float4 rv = R4[il];
        float dx = rv.x - qx, dy = rv.y - qy, dz = rv.z - qz;
        float d  = sqrtf(fmaxf(dx*dx + dy*dy + dz*dz, 1e-12f));
        size_t base = ((size_t)(b * NPTS + n)) * NB + phase * KNN + lane;
        g_feats[base] = make_float4(dx, dy, dz, d);
        g_grp[base*3 + 0] = rv.x;
        g_grp[base*3 + 1] = rv.y;
        g_grp[base*3 + 2] = rv.z;
    }
}

// ---------------- fused fold + MLP + max + softmax + weighted sum --------------
// (unchanged: validated at 316.6 us)
#define SMEMF 13056

__device__ __forceinline__ void layer01(float4 x,
                                        const float* __restrict__ sW0,
                                        const float* __restrict__ sb0,
                                        const float* __restrict__ sW1,
                                        const float* __restrict__ sb1,
                                        u64 h1p[32])
{
    u64 h0p[32];
    #pragma unroll 4
    for (int c = 0; c < 64; c += 2) {
        float4 wa = ((const float4*)sW0)[c];
        float4 wb = ((const float4*)sW0)[c + 1];
        float a = fmaf(wa.x, x.x, fmaf(wa.y, x.y, fmaf(wa.z, x.z, fmaf(wa.w, x.w, sb0[c]))));
        float b = fmaf(wb.x, x.x, fmaf(wb.y, x.y, fmaf(wb.z, x.z, fmaf(wb.w, x.w, sb0[c+1]))));
        h0p[c >> 1] = pack2(fmaxf(a, 0.f), fmaxf(b, 0.f));
    }
    #pragma unroll 2
    for (int c = 0; c < 64; c += 2) {
        const ulonglong2* wr0 = (const ulonglong2*)(sW1 + c * 64);
        const ulonglong2* wr1 = (const ulonglong2*)(sW1 + (c + 1) * 64);
        u64 a0 = 0ull, a1 = 0ull, b0 = 0ull, b1 = 0ull;
        #pragma unroll
        for (int j = 0; j < 16; j++) {
            ulonglong2 w0 = wr0[j];
            ulonglong2 w1 = wr1[j];
            a0 = fma2(w0.x, h0p[2*j],     a0);
            a1 = fma2(w0.y, h0p[2*j + 1], a1);
            b0 = fma2(w1.x, h0p[2*j],     b0);
            b1 = fma2(w1.y, h0p[2*j + 1], b1);
        }
        float alo, ahi, blo, bhi;
        unpack2(add2(a0, a1), alo, ahi);
        unpack2(add2(b0, b1), blo, bhi);
        h1p[c >> 1] = pack2(fmaxf(sb1[c]   + alo + ahi, 0.f),
                            fmaxf(sb1[c+1] + blo + bhi, 0.f));
    }
}

__global__ __launch_bounds__(128) void mlp_k(float* __restrict__ out,
    const float* __restrict__ w0, const float* __restrict__ b0,
    const float* __restrict__ g0, const float* __restrict__ be0,
    const float* __restrict__ m0, const float* __restrict__ v0,
    const float* __restrict__ w1, const float* __restrict__ b1,
    const float* __restrict__ g1, const float* __restrict__ be1,
    const float* __restrict__ m1, const float* __restrict__ v1,
    const float* __restrict__ w2, const float* __restrict__ b2,
    const float* __restrict__ g2, const float* __restrict__ be2,
    const float* __restrict__ m2, const float* __restrict__ v2)
{
    extern __shared__ float sm[];
    float* sW1 = sm;
    float* sW2 = sm + 4096;
    float* sW0 = sm + 12288;
    float* sb0 = sm + 12544;
    float* sb1 = sm + 12608;
    float* sb2 = sm + 12672;
    float* sS0 = sm + 12800;
    float* sS1 = sm + 12864;
    float* sS2 = sm + 12928;

    const int tid = threadIdx.x;

    if (tid < 64) {
        float s = g0[tid] * rsqrtf(v0[tid] + 1e-3f);
        sS0[tid] = s; sb0[tid] = (b0[tid] - m0[tid]) * s + be0[tid];
        float t = g1[tid] * rsqrtf(v1[tid] + 1e-3f);
        sS1[tid] = t; sb1[tid] = (b1[tid] - m1[tid]) * t + be1[tid];
    }
    if (tid < 128) {
        float s = g2[tid] * rsqrtf(v2[tid] + 1e-3f);
        sS2[tid] = s; sb2[tid] = (b2[tid] - m2[tid]) * s + be2[tid];
    }
    __syncthreads();
    for (int i = tid; i < 4096; i += 128) sW1[i] = w1[i] * sS1[i >> 6];
    for (int i = tid; i < 8192; i += 128) sW2[i] = w2[i] * sS2[i >> 6];
    for (int i = tid; i < 256;  i += 128) sW0[i] = w0[i] * sS0[i >> 2];
    __syncthreads();

    const int warp = tid >> 5;
    const int lane = tid & 31;
    const int pt   = blockIdx.x * 8 + warp * 2 + (lane >> 4);
    const int nb   = lane & 15;

    const size_t pixA = (size_t)pt * NB + nb;
    const size_t pixB = pixA + 16;

    u64 h1pA[32], h1pB[32];
    layer01(g_feats[pixA], sW0, sb0, sW1, sb1, h1pA);
    layer01(g_feats[pixB], sW0, sb0, sW1, sb1, h1pB);

    float mxA = -__int_as_float(0x7f800000);
    float mxB = mxA;
    #pragma unroll 2
    for (int c = 0; c < 128; c++) {
        const ulonglong2* wr = (const ulonglong2*)(sW2 + c * 64);
        u64 a0 = 0ull, a1 = 0ull, c0 = 0ull, c1 = 0ull;
        #pragma unroll
        for (int j = 0; j < 16; j++) {
            ulonglong2 w = wr[j];
            a0 = fma2(w.x, h1pA[2*j],     a0);
            a1 = fma2(w.y, h1pA[2*j + 1], a1);
            c0 = fma2(w.x, h1pB[2*j],     c0);
            c1 = fma2(w.y, h1pB[2*j + 1], c1);
        }
        float alo, ahi, blo, bhi;
        unpack2(add2(a0, a1), alo, ahi);
        unpack2(add2(c0, c1), blo, bhi);
        float bias = sb2[c];
        mxA = fmaxf(mxA, fmaxf(bias + alo + ahi, 0.f));
        mxB = fmaxf(mxB, fmaxf(bias + blo + bhi, 0.f));
    }

    float M = fmaxf(mxA, mxB);
    #pragma unroll
    for (int o = 8; o; o >>= 1) M = fmaxf(M, __shfl_xor_sync(0xffffffffu, M, o));
    float eA = expf(mxA - M);
    float eB = expf(mxB - M);
    float S = eA + eB;
    #pragma unroll
    for (int o = 8; o; o >>= 1) S += __shfl_xor_sync(0xffffffffu, S, o);
    float wA = eA / S;
    float wB = eB / S;

    size_t ga = pixA * 3, gb = pixB * 3;
    float sx = fmaf(wA, g_grp[ga + 0], wB * g_grp[gb + 0]);
    float sy = fmaf(wA, g_grp[ga + 1], wB * g_grp[gb + 1]);
    float sz = fmaf(wA, g_grp[ga + 2], wB * g_grp[gb + 2]);
    #pragma unroll
    for (int o = 8; o; o >>= 1) {
        sx += __shfl_xor_sync(0xffffffffu, sx, o);
        sy += __shfl_xor_sync(0xffffffffu, sy, o);
        sz += __shfl_xor_sync(0xffffffffu, sz, o);
    }
    if (nb == 0) {
        int b = pt >> 12;
        int n = pt & (NPTS - 1);
        out[(b*3 + 0) * NPTS + n] = sx;
        out[(b*3 + 1) * NPTS + n] = sy;
        out[(b*3 + 2) * NPTS + n] = sz;
    }
}

// ---------------- launch ----------------
extern "C" void kernel_launch(void* const* d_in, const int* in_sizes, int n_in,
                              void* d_out, int out_size)
{
    const float* p1 = (const float*)d_in[0];
    const float* p2 = (const float*)d_in[1];
    // d_in[2] = k (fixed at 16)
    const float* w0  = (const float*)d_in[3];
    const float* b0  = (const float*)d_in[4];
    const float* g0  = (const float*)d_in[5];
    const float* be0 = (const float*)d_in[6];
    const float* m0  = (const float*)d_in[7];
    const float* v0  = (const float*)d_in[8];
    const float* w1  = (const float*)d_in[9];
    const float* b1  = (const float*)d_in[10];
    const float* g1  = (const float*)d_in[11];
    const float* be1 = (const float*)d_in[12];
    const float* m1  = (const float*)d_in[13];
    const float* v1  = (const float*)d_in[14];
    const float* w2  = (const float*)d_in[15];
    const float* b2  = (const float*)d_in[16];
    const float* g2  = (const float*)d_in[17];
    const float* be2 = (const float*)d_in[18];
    const float* m2  = (const float*)d_in[19];
    const float* v2  = (const float*)d_in[20];

    cudaFuncSetAttribute(mlp_k, cudaFuncAttributeMaxDynamicSharedMemorySize,
                         SMEMF * (int)sizeof(float));

    pack_k<<<2*BATCH*NPTS/256, 256>>>(p1, p2);

    knn_w<<<dim3(NPTS/8, BATCH, 2), 256>>>(p1);

    mlp_k<<<BATCH*NPTS/8, 128, SMEMF * (int)sizeof(float)>>>((float*)d_out,
        w0, b0, g0, be0, m0, v0,
        w1, b1, g1, be1, m1, v1,
        w2, b2, g2, be2, m2, v2);
}